// round 1
// baseline (speedup 1.0000x reference)
#include <cuda_runtime.h>
#include <cuda_bf16.h>
#include <stdint.h>

// Problem constants (fixed by the reference)
#define BATCH 1024
#define IN_SIZE 2048
#define OUT_SIZE 2048
#define EMAX 131072

// -------- device scratch (no allocations allowed) --------
__device__ float g_xT[IN_SIZE * BATCH];      // 8 MB  : x transposed [in][batch]
__device__ float g_outT[OUT_SIZE * BATCH];   // 8 MB  : out transposed [out][batch]
__device__ int   g_cnt[OUT_SIZE];
__device__ int   g_off[OUT_SIZE + 1];
__device__ int   g_cur[OUT_SIZE];
__device__ int   g_srt_i[EMAX];
__device__ float g_srt_w[EMAX];
__device__ int   g_idx64;                    // 1 if indices are int64, 0 if int32

__device__ __forceinline__ int fetch_idx(const void* p, int e, int is64) {
    if (is64) return (int)(((const long long*)p)[e]);
    return ((const int*)p)[e];
}

// -------- 1. detect index dtype --------
__global__ void detect_kernel(const void* in_idx, int E) {
    if (threadIdx.x == 0) {
        const long long* q = (const long long*)in_idx;
        int n = E < 32 ? E : 32;
        bool ok64 = true;
        for (int k = 0; k < n; k++) {
            long long v = q[k];
            if (v < 0 || v >= IN_SIZE) { ok64 = false; break; }
        }
        g_idx64 = ok64 ? 1 : 0;
    }
}

// -------- 2a. zero counters --------
__global__ void zero_kernel() {
    int t = blockIdx.x * blockDim.x + threadIdx.x;
    if (t < OUT_SIZE) { g_cnt[t] = 0; }
}

// -------- 2b. histogram over out_idx --------
__global__ void hist_kernel(const void* out_idx, int E) {
    int is64 = g_idx64;
    for (int e = blockIdx.x * blockDim.x + threadIdx.x; e < E;
         e += gridDim.x * blockDim.x) {
        int o = fetch_idx(out_idx, e, is64);
        atomicAdd(&g_cnt[o], 1);
    }
}

// -------- 2c. exclusive scan of 2048 counters (one block, 1024 threads) ------
__global__ void scan_kernel() {
    __shared__ int s[1024];
    int t = threadIdx.x;

    // first half [0,1024)
    int a = g_cnt[t];
    s[t] = a;
    __syncthreads();
    for (int off = 1; off < 1024; off <<= 1) {
        int v = (t >= off) ? s[t - off] : 0;
        __syncthreads();
        s[t] += v;
        __syncthreads();
    }
    int inc_a = s[t];
    int totA = s[1023];
    __syncthreads();

    // second half [1024,2048)
    int b = g_cnt[t + 1024];
    s[t] = b;
    __syncthreads();
    for (int off = 1; off < 1024; off <<= 1) {
        int v = (t >= off) ? s[t - off] : 0;
        __syncthreads();
        s[t] += v;
        __syncthreads();
    }
    int inc_b = s[t] + totA;

    int ex_a = inc_a - a;
    int ex_b = inc_b - b;
    g_off[t] = ex_a;
    g_off[t + 1024] = ex_b;
    g_cur[t] = ex_a;
    g_cur[t + 1024] = ex_b;
    if (t == 1023) g_off[2048] = inc_b;
}

// -------- 2d. scatter edges into CSR order --------
__global__ void scatter_kernel(const void* in_idx, const void* out_idx,
                               const float* w, int E) {
    int is64 = g_idx64;
    for (int e = blockIdx.x * blockDim.x + threadIdx.x; e < E;
         e += gridDim.x * blockDim.x) {
        int o = fetch_idx(out_idx, e, is64);
        int i = fetch_idx(in_idx, e, is64);
        int pos = atomicAdd(&g_cur[o], 1);
        g_srt_i[pos] = i;
        g_srt_w[pos] = w[e];
    }
}

// -------- 3. transpose x [B][IN] -> xT [IN][B] --------
__global__ void transpose_x_kernel(const float* __restrict__ x) {
    __shared__ float tile[32][33];
    int ix = blockIdx.x * 32 + threadIdx.x;  // input-dim index
    int ib = blockIdx.y * 32 + threadIdx.y;  // batch index
#pragma unroll
    for (int j = 0; j < 4; j++)
        tile[threadIdx.y + 8 * j][threadIdx.x] = x[(ib + 8 * j) * IN_SIZE + ix];
    __syncthreads();
    int ob = blockIdx.y * 32 + threadIdx.x;  // batch now contiguous
    int oi = blockIdx.x * 32 + threadIdx.y;  // input-dim
#pragma unroll
    for (int j = 0; j < 4; j++)
        g_xT[(oi + 8 * j) * BATCH + ob] = tile[threadIdx.x][threadIdx.y + 8 * j];
}

// -------- 4. main SpMM: one block per output column --------
__global__ void __launch_bounds__(256) spmm_kernel() {
    int o = blockIdx.x;
    int s = g_off[o];
    int e = g_off[o + 1];
    int t = threadIdx.x;

    __shared__ int   si[256];
    __shared__ float sw[256];

    float4 acc = make_float4(0.f, 0.f, 0.f, 0.f);

    for (int base = s; base < e; base += 256) {
        int k = base + t;
        if (k < e) { si[t] = g_srt_i[k]; sw[t] = g_srt_w[k]; }
        __syncthreads();
        int m = e - base;
        if (m > 256) m = 256;
        for (int j = 0; j < m; j++) {
            const float4 v = *reinterpret_cast<const float4*>(
                &g_xT[si[j] * BATCH + (t << 2)]);
            float w = sw[j];
            acc.x += w * v.x;
            acc.y += w * v.y;
            acc.z += w * v.z;
            acc.w += w * v.w;
        }
        __syncthreads();
    }
    *reinterpret_cast<float4*>(&g_outT[o * BATCH + (t << 2)]) = acc;
}

// -------- 5. transpose outT [OUT][B] -> out [B][OUT] --------
__global__ void transpose_out_kernel(float* __restrict__ out) {
    __shared__ float tile[32][33];
    int ib = blockIdx.x * 32 + threadIdx.x;  // batch index (contiguous in outT)
    int io = blockIdx.y * 32 + threadIdx.y;  // output index
#pragma unroll
    for (int j = 0; j < 4; j++)
        tile[threadIdx.y + 8 * j][threadIdx.x] =
            g_outT[(io + 8 * j) * BATCH + ib];
    __syncthreads();
    int oo = blockIdx.y * 32 + threadIdx.x;  // output now contiguous
    int ob = blockIdx.x * 32 + threadIdx.y;  // batch
#pragma unroll
    for (int j = 0; j < 4; j++)
        out[(ob + 8 * j) * OUT_SIZE + oo] = tile[threadIdx.x][threadIdx.y + 8 * j];
}

extern "C" void kernel_launch(void* const* d_in, const int* in_sizes, int n_in,
                              void* d_out, int out_size) {
    const float* x       = (const float*)d_in[0];
    const float* weights = (const float*)d_in[1];
    const void*  in_idx  = d_in[2];
    const void*  out_idx = d_in[3];
    float* out = (float*)d_out;
    int E = in_sizes[1];  // weights element count == number of edges
    if (E > EMAX) E = EMAX;

    // 1. detect index dtype (int32 vs int64)
    detect_kernel<<<1, 32>>>(in_idx, E);

    // 2. build CSR by output column
    zero_kernel<<<(OUT_SIZE + 255) / 256, 256>>>();
    hist_kernel<<<256, 256>>>(out_idx, E);
    scan_kernel<<<1, 1024>>>();
    scatter_kernel<<<256, 256>>>(in_idx, out_idx, weights, E);

    // 3. transpose x -> xT
    {
        dim3 grid(IN_SIZE / 32, BATCH / 32);
        dim3 block(32, 8);
        transpose_x_kernel<<<grid, block>>>(x);
    }

    // 4. main gather-reduce (one block per output column)
    spmm_kernel<<<OUT_SIZE, 256>>>();

    // 5. transpose outT -> out
    {
        dim3 grid(BATCH / 32, OUT_SIZE / 32);
        dim3 block(32, 8);
        transpose_out_kernel<<<grid, block>>>(out);
    }
}